// round 12
// baseline (speedup 1.0000x reference)
#include <cuda_runtime.h>
#include <cuda_bf16.h>
#include <cuda_fp16.h>

// ---------------------------------------------------------------------------
// NT-Xent loss, N=8192, D=512. FP8 (e4m3, scale 16) mma.sync m16n8k32 with
// f16 accumulation (2x rate), upper-triangular tiles (S = Z Z^T symmetric).
// Epilogue in f16x2 (ex2.approx.f16x2), exponent biased +15 so all relevant
// values stay f16-normal; bias removed in the final log.
// 296 CTAs x 512 threads, 2 CTAs/SM; depth-3 cp.async B ring (CP_WAIT(1)).
// ---------------------------------------------------------------------------

#define NN      8192
#define DD      512
#define BHALF   4096
#define NCHUNK  4            // 512 fp8 bytes / 128-byte chunk
#define NTILES  2080
#define NCTAS   296
#define NTHR    512

#define PSC     0.00390625f               // 1/256
#define INV_TAU 14.285714285714286f
// f16 constants: E = rn16(log2e/0.07/256) = 0x2D27, C = rn16(20.60993-15) = 0xC59C
#define E2U     0x2D272D27u
#define NC2U    0xC59CC59Cu
// final log correction: ln2 * (15 + (20.6099291555662-15) - 5.609375)
#define LOGC    10.3975918f

#define A_BYTES  65536       // 128 rows x 512 B (4 chunks x 16 KB)
#define B_OFF    65536
#define B_BYTES  16384       // one B chunk: 128 rows x 128 B
#define NBUF     3
#define SMEM_BYTES (A_BYTES + NBUF*B_BYTES + 128)

__device__ __align__(128) unsigned char g_z[(size_t)NN * DD];   // e4m3, x16
__device__ float g_rowsum[NN];
__device__ float g_pos[NN];
__device__ unsigned g_done;

// ------------------------------- helpers -----------------------------------
__device__ __forceinline__ unsigned smem_u32(const void* p) {
    unsigned a;
    asm("{ .reg .u64 t; cvta.to.shared.u64 t, %1; cvt.u32.u64 %0, t; }"
        : "=r"(a) : "l"(p));
    return a;
}
__device__ __forceinline__ unsigned swz(unsigned off) {
    return off ^ ((off >> 3) & 0x70);
}
__device__ __forceinline__ void cp16(unsigned dst, const void* src) {
    asm volatile("cp.async.cg.shared.global [%0], [%1], 16;"
                 :: "r"(dst), "l"(src) : "memory");
}
#define CP_COMMIT() asm volatile("cp.async.commit_group;" ::: "memory")
#define CP_WAIT(n)  asm volatile("cp.async.wait_group %0;" :: "n"(n) : "memory")

__device__ __forceinline__ void ldsm_x4(unsigned* r, unsigned addr) {
    asm volatile("ldmatrix.sync.aligned.m8n8.x4.shared.b16 {%0,%1,%2,%3}, [%4];"
                 : "=r"(r[0]), "=r"(r[1]), "=r"(r[2]), "=r"(r[3]) : "r"(addr));
}
// fp8 mma, f16 accumulator (c0: rows lane>>2, cols 2*(lane&3)+{0,1}; c1: row+8)
__device__ __forceinline__ void mma_fp8h(unsigned* c, const unsigned* a,
                                         unsigned b0, unsigned b1) {
    asm volatile(
        "mma.sync.aligned.m16n8k32.row.col.f16.e4m3.e4m3.f16 "
        "{%0,%1}, {%2,%3,%4,%5}, {%6,%7}, {%0,%1};"
        : "+r"(c[0]), "+r"(c[1])
        : "r"(a[0]), "r"(a[1]), "r"(a[2]), "r"(a[3]), "r"(b0), "r"(b1));
}
__device__ __forceinline__ unsigned hfma2u(unsigned a, unsigned b, unsigned c) {
    unsigned d; asm("fma.rn.f16x2 %0,%1,%2,%3;" : "=r"(d) : "r"(a), "r"(b), "r"(c));
    return d;
}
__device__ __forceinline__ unsigned hadd2u(unsigned a, unsigned b) {
    unsigned d; asm("add.rn.f16x2 %0,%1,%2;" : "=r"(d) : "r"(a), "r"(b));
    return d;
}
__device__ __forceinline__ unsigned h2ex2(unsigned a) {
    unsigned d; asm("ex2.approx.f16x2 %0,%1;" : "=r"(d) : "r"(a));
    return d;
}
__device__ __forceinline__ float2 h2f2(unsigned a) {
    __half2 h = *(__half2*)&a;
    return __half22float2(h);
}
__device__ __forceinline__ unsigned short cvt2_e4m3(float lo, float hi) {
    unsigned short r;
    asm("cvt.rn.satfinite.e4m3x2.f32 %0, %1, %2;" : "=h"(r) : "f"(hi), "f"(lo));
    return r;
}

// decode flattened tile index -> (I, J)
__device__ __forceinline__ void tile_decode(int t, int& I, int& J) {
    int p = t / 65;
    int l = t - p * 65;
    int n1 = 64 - p;
    if (l < n1) { I = p;      J = p + l; }
    else        { I = 63 - p; J = I + (l - n1); }
}

// ------------------------- kernel 1: normalize -> fp8 ----------------------
__global__ __launch_bounds__(256) void ntx_normalize(const float* __restrict__ anchor,
                                                     const float* __restrict__ positive) {
    int gt = blockIdx.x * 256 + threadIdx.x;
    if (gt < NN) g_rowsum[gt] = 0.f;          // graph-replay safe re-init
    if (gt == 0) g_done = 0u;

    int row  = blockIdx.x * 8 + (threadIdx.x >> 5);
    int lane = threadIdx.x & 31;
    const float* src = (row < BHALF) ? (anchor + (size_t)row * DD)
                                     : (positive + (size_t)(row - BHALF) * DD);
    const float4* s4 = (const float4*)src;
    float4 v[4];
    float ss = 0.f;
#pragma unroll
    for (int q = 0; q < 4; q++) {
        v[q] = s4[lane + 32 * q];
        ss += v[q].x * v[q].x + v[q].y * v[q].y + v[q].z * v[q].z + v[q].w * v[q].w;
    }
#pragma unroll
    for (int o = 16; o > 0; o >>= 1) ss += __shfl_xor_sync(0xFFFFFFFFu, ss, o);
    float s16 = 16.0f / fmaxf(sqrtf(ss), 1e-8f);

    unsigned* zp = (unsigned*)(g_z + (size_t)row * DD);
#pragma unroll
    for (int q = 0; q < 4; q++) {
        unsigned lo = cvt2_e4m3(v[q].x * s16, v[q].y * s16);
        unsigned hi = cvt2_e4m3(v[q].z * s16, v[q].w * s16);
        zp[lane + 32 * q] = lo | (hi << 16);
    }
}

// ------------------------- kernel 2: upper-tri GEMM + exp-reduce -----------
__device__ __forceinline__ void issueB(unsigned bbase, int colbase, int k, int tid) {
#pragma unroll
    for (int it = 0; it < 2; it++) {
        int idx = tid + it * NTHR;
        int r = idx >> 3, c8 = idx & 7;
        const void* src = g_z + ((size_t)(colbase + r) << 9) + k * 128 + c8 * 16;
        cp16(bbase + swz((unsigned)(r * 128 + c8 * 16)), src);
    }
}

// depth-3 ring: slot = m % 3
__device__ __forceinline__ void issue_chunk(unsigned Bb, int t0, int t1, int m, int tid) {
    int tt = t0 + (m >> 2);
    if (tt < t1) {
        int I2, J2;
        tile_decode(tt, I2, J2);
        issueB(Bb + (unsigned)(m % NBUF) * B_BYTES, J2 << 7, m & 3, tid);
    }
    CP_COMMIT();
}

__global__ __launch_bounds__(NTHR, 2) void ntx_main(float* __restrict__ out) {
    extern __shared__ char smem_raw[];
    unsigned raw  = smem_u32(smem_raw);
    unsigned base = (raw + 127u) & ~127u;
    char* sp      = smem_raw + (base - raw);
    unsigned A  = base;
    unsigned Bb = base + B_OFF;

    int tid  = threadIdx.x;
    int wid  = tid >> 5, lane = tid & 31;
    int warpM = wid & 3, warpN = wid >> 2;     // 4 x 4 warp grid, tile 32x32
    int qrow = lane >> 2;

    int c  = blockIdx.x;
    int t0 = (c * NTILES) / NCTAS;
    int t1 = ((c + 1) * NTILES) / NCTAS;

    // compact ldmatrix addressing
    int sel = lane >> 3, lr = lane & 7;
    unsigned cbx[4];
#pragma unroll
    for (int ks = 0; ks < 4; ks++)
        cbx[ks] = ((unsigned)(ks * 32 + ((sel >> 1) << 4))) ^ ((unsigned)lr << 4);
    unsigned arowb[2];
#pragma unroll
    for (int mf = 0; mf < 2; mf++)
        arowb[mf] = (unsigned)((warpM * 32 + mf * 16 + ((sel & 1) << 3) + lr) * 128);
    unsigned browb[2];
#pragma unroll
    for (int p = 0; p < 2; p++)
        browb[p] = (unsigned)((warpN * 32 + p * 16 + ((sel & 1) << 3) + lr) * 128);

    // prologue: prefetch chunks 0, 1
    issue_chunk(Bb, t0, t1, 0, tid);
    issue_chunk(Bb, t0, t1, 1, tid);

    unsigned acc[2][4][2];                     // f16x2 accumulators (32x32 tile)
    float rsum[2][2] = {{0.f, 0.f}, {0.f, 0.f}};
    int curI = -1;
    int cm = 0;

    for (int t = t0; t < t1; t++) {
        int I, J;
        tile_decode(t, I, J);
        int rowbase = I << 7, colbase = J << 7;

        if (I != curI) {
            if (curI >= 0) {
#pragma unroll
                for (int mf = 0; mf < 2; mf++)
#pragma unroll
                    for (int h = 0; h < 2; h++) {
                        float v = rsum[mf][h];
                        v += __shfl_xor_sync(0xFFFFFFFFu, v, 1);
                        v += __shfl_xor_sync(0xFFFFFFFFu, v, 2);
                        if ((lane & 3) == 0)
                            atomicAdd(&g_rowsum[(curI << 7) + warpM * 32 + mf * 16 + h * 8 + qrow], v);
                        rsum[mf][h] = 0.f;
                    }
            }
            __syncthreads();                   // all readers of old A done
#pragma unroll
            for (int it = 0; it < 8; it++) {
                int x = tid + it * NTHR;
                int r = x >> 5, u = x & 31, ck = u >> 3, c8 = u & 7;
                const uint4* src = (const uint4*)(g_z + ((size_t)(rowbase + r) << 9)
                                                  + ck * 128 + c8 * 16);
                *(uint4*)(sp + ck * 16384 + swz((unsigned)(r * 128 + c8 * 16))) = *src;
            }
            __syncthreads();
            curI = I;
        }

#pragma unroll
        for (int mf = 0; mf < 2; mf++)
#pragma unroll
            for (int nf = 0; nf < 4; nf++) {
                acc[mf][nf][0] = 0u;
                acc[mf][nf][1] = 0u;
            }

#pragma unroll
        for (int k = 0; k < NCHUNK; k++) {
            CP_WAIT(1);                        // chunk cm landed (cm+1 may fly)
            __syncthreads();
            // chunk cm+2 overwrites slot of cm-1 (readers done pre-barrier)
            issue_chunk(Bb, t0, t1, cm + 2, tid);

            unsigned Ac = A + k * 16384;
            unsigned Bc = Bb + (unsigned)(cm % NBUF) * B_BYTES;
#pragma unroll
            for (int ks = 0; ks < 4; ks++) {
                unsigned afr[2][4];
                ldsm_x4(afr[0], Ac + arowb[0] + cbx[ks]);
                ldsm_x4(afr[1], Ac + arowb[1] + cbx[ks]);
                unsigned bfr[2][4];
                ldsm_x4(bfr[0], Bc + browb[0] + cbx[ks]);
                ldsm_x4(bfr[1], Bc + browb[1] + cbx[ks]);
#pragma unroll
                for (int mf = 0; mf < 2; mf++)
#pragma unroll
                    for (int nf = 0; nf < 4; nf++)
                        mma_fp8h(acc[mf][nf], afr[mf],
                                 bfr[nf >> 1][nf & 1],
                                 bfr[nf >> 1][2 + (nf & 1)]);
            }
            cm++;
        }

        // ---- epilogue (f16x2, exponent biased +15) ----
        bool isdiag = (J == I);
        bool ispos  = (J == I + 32);

        unsigned rs2[2][2] = {{0u, 0u}, {0u, 0u}};
        unsigned cp2[4] = {0u, 0u, 0u, 0u};
#pragma unroll
        for (int mf = 0; mf < 2; mf++)
#pragma unroll
            for (int nf = 0; nf < 4; nf++) {
                unsigned e0 = h2ex2(hfma2u(acc[mf][nf][0], E2U, NC2U));
                unsigned e1 = h2ex2(hfma2u(acc[mf][nf][1], E2U, NC2U));
                rs2[mf][0] = hadd2u(rs2[mf][0], e0);
                rs2[mf][1] = hadd2u(rs2[mf][1], e1);
                cp2[nf]    = hadd2u(cp2[nf], hadd2u(e0, e1));
            }
#pragma unroll
        for (int mf = 0; mf < 2; mf++)
#pragma unroll
            for (int h = 0; h < 2; h++) {
                float2 f = h2f2(rs2[mf][h]);
                rsum[mf][h] += f.x + f.y;
            }

        if (isdiag | ispos) {
#pragma unroll
            for (int mf = 0; mf < 2; mf++)
#pragma unroll
                for (int h = 0; h < 2; h++) {
                    int rloc = warpM * 32 + mf * 16 + h * 8 + qrow;
                    int cc = rloc - warpN * 32;
                    if (cc >= 0 && cc < 32 && (((cc >> 1) & 3) == (lane & 3))) {
                        unsigned hp = acc[mf][cc >> 3][h];
                        if (isdiag) {
                            // identical f16 recompute -> bitwise-exact cancel
                            float2 fe = h2f2(h2ex2(hfma2u(hp, E2U, NC2U)));
                            rsum[mf][h] -= (cc & 1) ? fe.y : fe.x;
                        }
                        if (ispos) {
                            __half2 hv = *(__half2*)&hp;
                            float v = (cc & 1) ? __high2float(hv) : __low2float(hv);
                            g_pos[rowbase + rloc] = v * PSC;
                            g_pos[rowbase + rloc + BHALF] = v * PSC;
                        }
                    }
                }
        }

        if (!isdiag) {
#pragma unroll
            for (int nf = 0; nf < 4; nf++) {
                unsigned v = cp2[nf];
                v = hadd2u(v, __shfl_xor_sync(0xFFFFFFFFu, v, 4));
                v = hadd2u(v, __shfl_xor_sync(0xFFFFFFFFu, v, 8));
                v = hadd2u(v, __shfl_xor_sync(0xFFFFFFFFu, v, 16));
                if (lane < 4) {
                    float2 f = h2f2(v);
                    int cb = colbase + warpN * 32 + nf * 8 + 2 * lane;
                    atomicAdd(&g_rowsum[cb],     f.x);
                    atomicAdd(&g_rowsum[cb + 1], f.y);
                }
            }
        }
    }

    // final row flush
#pragma unroll
    for (int mf = 0; mf < 2; mf++)
#pragma unroll
        for (int h = 0; h < 2; h++) {
            float v = rsum[mf][h];
            v += __shfl_xor_sync(0xFFFFFFFFu, v, 1);
            v += __shfl_xor_sync(0xFFFFFFFFu, v, 2);
            if ((lane & 3) == 0 && curI >= 0)
                atomicAdd(&g_rowsum[(curI << 7) + warpM * 32 + mf * 16 + h * 8 + qrow], v);
        }

    // ---- completion ticket: last CTA computes the loss ----
    __threadfence();
    __syncthreads();
    __shared__ unsigned ticket;
    if (tid == 0) ticket = atomicAdd(&g_done, 1u);
    __syncthreads();
    if (ticket == NCTAS - 1) {
        float local = 0.f;
        for (int r = tid; r < NN; r += NTHR)
            local += (1.0f - g_pos[r]) * INV_TAU + __logf(g_rowsum[r]) - LOGC;
#pragma unroll
        for (int o = 16; o > 0; o >>= 1) local += __shfl_xor_sync(0xFFFFFFFFu, local, o);
        __shared__ float red[16];
        if (lane == 0) red[wid] = local;
        __syncthreads();
        if (tid < 16) {
            float v = red[tid];
#pragma unroll
            for (int o = 8; o > 0; o >>= 1) v += __shfl_xor_sync(0xFFFFu, v, o);
            if (tid == 0) out[0] = v * (1.0f / (float)NN);
        }
    }
}

// ---------------------------------------------------------------------------
extern "C" void kernel_launch(void* const* d_in, const int* in_sizes, int n_in,
                              void* d_out, int out_size) {
    (void)in_sizes; (void)n_in; (void)out_size;
    const float* anchor   = (const float*)d_in[0];
    const float* positive = (const float*)d_in[1];

    cudaFuncSetAttribute(ntx_main, cudaFuncAttributeMaxDynamicSharedMemorySize,
                         SMEM_BYTES);

    ntx_normalize<<<NN / 8, 256>>>(anchor, positive);
    ntx_main<<<NCTAS, NTHR, SMEM_BYTES>>>((float*)d_out);
}

// round 13
// speedup vs baseline: 1.0158x; 1.0158x over previous
#include <cuda_runtime.h>
#include <cuda_bf16.h>
#include <cuda_fp16.h>

// ---------------------------------------------------------------------------
// NT-Xent loss, N=8192, D=512. FP8 (e4m3, scale 16) mma.sync m16n8k32 with
// f16 accumulation (2x rate), upper-triangular tiles (S = Z Z^T symmetric).
// 296 CTAs x 512 threads, 2 CTAs/SM. B rows are PARTITIONED by warp group
// (warpN): each 4-warp group loads and consumes only its own 32-row quarter
// of each B chunk, synchronized by a group-local named barrier -> no CTA-wide
// sync in the K-loop. Depth-3 cp.async ring, CP_WAIT(1). f32 epilogue.
// ---------------------------------------------------------------------------

#define NN      8192
#define DD      512
#define BHALF   4096
#define NCHUNK  4            // 512 fp8 bytes / 128-byte chunk
#define NTILES  2080
#define NCTAS   296
#define NTHR    512

#define K1F     20.60992915555662f        // log2(e)/0.07
#define EXSC    0.08050753576389304f      // K1F / 256   (fp8 scale^2)
#define PSC     0.00390625f               // 1/256
#define INV_TAU 14.285714285714286f

#define A_BYTES  65536       // 128 rows x 512 B (4 chunks x 16 KB)
#define B_OFF    65536
#define B_BYTES  16384       // one B chunk: 128 rows x 128 B
#define NBUF     3
#define SMEM_BYTES (A_BYTES + NBUF*B_BYTES + 128)

__device__ __align__(128) unsigned char g_z[(size_t)NN * DD];   // e4m3, x16
__device__ float g_rowsum[NN];
__device__ float g_pos[NN];
__device__ unsigned g_done;

// ------------------------------- helpers -----------------------------------
__device__ __forceinline__ unsigned smem_u32(const void* p) {
    unsigned a;
    asm("{ .reg .u64 t; cvta.to.shared.u64 t, %1; cvt.u32.u64 %0, t; }"
        : "=r"(a) : "l"(p));
    return a;
}
__device__ __forceinline__ unsigned swz(unsigned off) {
    return off ^ ((off >> 3) & 0x70);
}
__device__ __forceinline__ void cp16(unsigned dst, const void* src) {
    asm volatile("cp.async.cg.shared.global [%0], [%1], 16;"
                 :: "r"(dst), "l"(src) : "memory");
}
#define CP_COMMIT() asm volatile("cp.async.commit_group;" ::: "memory")
#define CP_WAIT(n)  asm volatile("cp.async.wait_group %0;" :: "n"(n) : "memory")
#define GBAR(id)    asm volatile("bar.sync %0, 128;" :: "r"(id) : "memory")

__device__ __forceinline__ void ldsm_x4(unsigned* r, unsigned addr) {
    asm volatile("ldmatrix.sync.aligned.m8n8.x4.shared.b16 {%0,%1,%2,%3}, [%4];"
                 : "=r"(r[0]), "=r"(r[1]), "=r"(r[2]), "=r"(r[3]) : "r"(addr));
}
// fp8 mma, f16 accumulator (c0: rows lane>>2, cols 2*(lane&3)+{0,1}; c1: row+8)
__device__ __forceinline__ void mma_fp8h(unsigned* c, const unsigned* a,
                                         unsigned b0, unsigned b1) {
    asm volatile(
        "mma.sync.aligned.m16n8k32.row.col.f16.e4m3.e4m3.f16 "
        "{%0,%1}, {%2,%3,%4,%5}, {%6,%7}, {%0,%1};"
        : "+r"(c[0]), "+r"(c[1])
        : "r"(a[0]), "r"(a[1]), "r"(a[2]), "r"(a[3]), "r"(b0), "r"(b1));
}
__device__ __forceinline__ float ex2s(float v) {   // exp((v/256 - 1)/tau)
    float y;
    asm("ex2.approx.ftz.f32 %0, %1;" : "=f"(y) : "f"(fmaf(v, EXSC, -K1F)));
    return y;
}
__device__ __forceinline__ unsigned short cvt2_e4m3(float lo, float hi) {
    unsigned short r;
    asm("cvt.rn.satfinite.e4m3x2.f32 %0, %1, %2;" : "=h"(r) : "f"(hi), "f"(lo));
    return r;
}

// decode flattened tile index -> (I, J)
__device__ __forceinline__ void tile_decode(int t, int& I, int& J) {
    int p = t / 65;
    int l = t - p * 65;
    int n1 = 64 - p;
    if (l < n1) { I = p;      J = p + l; }
    else        { I = 63 - p; J = I + (l - n1); }
}

// ------------------------- kernel 1: normalize -> fp8 ----------------------
__global__ __launch_bounds__(256) void ntx_normalize(const float* __restrict__ anchor,
                                                     const float* __restrict__ positive) {
    int gt = blockIdx.x * 256 + threadIdx.x;
    if (gt < NN) g_rowsum[gt] = 0.f;          // graph-replay safe re-init
    if (gt == 0) g_done = 0u;

    int row  = blockIdx.x * 8 + (threadIdx.x >> 5);
    int lane = threadIdx.x & 31;
    const float* src = (row < BHALF) ? (anchor + (size_t)row * DD)
                                     : (positive + (size_t)(row - BHALF) * DD);
    const float4* s4 = (const float4*)src;
    float4 v[4];
    float ss = 0.f;
#pragma unroll
    for (int q = 0; q < 4; q++) {
        v[q] = s4[lane + 32 * q];
        ss += v[q].x * v[q].x + v[q].y * v[q].y + v[q].z * v[q].z + v[q].w * v[q].w;
    }
#pragma unroll
    for (int o = 16; o > 0; o >>= 1) ss += __shfl_xor_sync(0xFFFFFFFFu, ss, o);
    float s16 = 16.0f / fmaxf(sqrtf(ss), 1e-8f);

    unsigned* zp = (unsigned*)(g_z + (size_t)row * DD);
#pragma unroll
    for (int q = 0; q < 4; q++) {
        unsigned lo = cvt2_e4m3(v[q].x * s16, v[q].y * s16);
        unsigned hi = cvt2_e4m3(v[q].z * s16, v[q].w * s16);
        zp[lane + 32 * q] = lo | (hi << 16);
    }
}

// ------------------------- kernel 2: upper-tri GEMM + exp-reduce -----------
// group gid (tid>>7) loads ONLY its 32-row quarter of B chunk k into the ring
__device__ __forceinline__ void issueB(unsigned bbase, int colbase, int k,
                                       int gid, int local) {
#pragma unroll
    for (int it = 0; it < 2; it++) {
        int idx = local + it * 128;            // 0..255 over 32 rows x 8 segs
        int rl = idx >> 3, c8 = idx & 7;
        int r  = gid * 32 + rl;
        const void* src = g_z + ((size_t)(colbase + r) << 9) + k * 128 + c8 * 16;
        cp16(bbase + swz((unsigned)(r * 128 + c8 * 16)), src);
    }
}

// depth-3 ring: slot = m % 3
__device__ __forceinline__ void issue_chunk(unsigned Bb, int t0, int t1, int m,
                                            int gid, int local) {
    int tt = t0 + (m >> 2);
    if (tt < t1) {
        int I2, J2;
        tile_decode(tt, I2, J2);
        issueB(Bb + (unsigned)(m % NBUF) * B_BYTES, J2 << 7, m & 3, gid, local);
    }
    CP_COMMIT();
}

__global__ __launch_bounds__(NTHR, 2) void ntx_main(float* __restrict__ out) {
    extern __shared__ char smem_raw[];
    unsigned raw  = smem_u32(smem_raw);
    unsigned base = (raw + 127u) & ~127u;
    char* sp      = smem_raw + (base - raw);
    unsigned A  = base;
    unsigned Bb = base + B_OFF;

    int tid  = threadIdx.x;
    int wid  = tid >> 5, lane = tid & 31;
    int warpM = wid & 3, warpN = wid >> 2;     // 4 x 4 warp grid, tile 32x32
    int gid   = tid >> 7;                      // == warpN (4-warp group)
    int local = tid & 127;
    int qrow = lane >> 2;

    int c  = blockIdx.x;
    int t0 = (c * NTILES) / NCTAS;
    int t1 = ((c + 1) * NTILES) / NCTAS;

    // compact ldmatrix addressing
    int sel = lane >> 3, lr = lane & 7;
    unsigned cbx[4];
#pragma unroll
    for (int ks = 0; ks < 4; ks++)
        cbx[ks] = ((unsigned)(ks * 32 + ((sel >> 1) << 4))) ^ ((unsigned)lr << 4);
    unsigned arowb[2];
#pragma unroll
    for (int mf = 0; mf < 2; mf++)
        arowb[mf] = (unsigned)((warpM * 32 + mf * 16 + ((sel & 1) << 3) + lr) * 128);
    unsigned browb[2];
#pragma unroll
    for (int p = 0; p < 2; p++)
        browb[p] = (unsigned)((warpN * 32 + p * 16 + ((sel & 1) << 3) + lr) * 128);

    // prologue: prefetch group's quarter of chunks 0, 1
    issue_chunk(Bb, t0, t1, 0, gid, local);
    issue_chunk(Bb, t0, t1, 1, gid, local);

    unsigned acc[2][4][2];                     // f16x2 accumulators (32x32 tile)
    float rsum[2][2] = {{0.f, 0.f}, {0.f, 0.f}};
    int curI = -1;
    int cm = 0;

    for (int t = t0; t < t1; t++) {
        int I, J;
        tile_decode(t, I, J);
        int rowbase = I << 7, colbase = J << 7;

        if (I != curI) {
            if (curI >= 0) {
#pragma unroll
                for (int mf = 0; mf < 2; mf++)
#pragma unroll
                    for (int h = 0; h < 2; h++) {
                        float v = rsum[mf][h];
                        v += __shfl_xor_sync(0xFFFFFFFFu, v, 1);
                        v += __shfl_xor_sync(0xFFFFFFFFu, v, 2);
                        if ((lane & 3) == 0)
                            atomicAdd(&g_rowsum[(curI << 7) + warpM * 32 + mf * 16 + h * 8 + qrow], v);
                        rsum[mf][h] = 0.f;
                    }
            }
            __syncthreads();                   // all readers of old A done
#pragma unroll
            for (int it = 0; it < 8; it++) {
                int x = tid + it * NTHR;
                int r = x >> 5, u = x & 31, ck = u >> 3, c8 = u & 7;
                const uint4* src = (const uint4*)(g_z + ((size_t)(rowbase + r) << 9)
                                                  + ck * 128 + c8 * 16);
                *(uint4*)(sp + ck * 16384 + swz((unsigned)(r * 128 + c8 * 16))) = *src;
            }
            __syncthreads();
            curI = I;
        }

#pragma unroll
        for (int mf = 0; mf < 2; mf++)
#pragma unroll
            for (int nf = 0; nf < 4; nf++) {
                acc[mf][nf][0] = 0u;
                acc[mf][nf][1] = 0u;
            }

#pragma unroll
        for (int k = 0; k < NCHUNK; k++) {
            CP_WAIT(1);                        // group's quarter of chunk cm landed
            GBAR(gid + 1);                     // group-local producer->consumer sync
            // group's quarter of chunk cm+2 overwrites its rows of slot cm-1
            issue_chunk(Bb, t0, t1, cm + 2, gid, local);

            unsigned Ac = A + k * 16384;
            unsigned Bc = Bb + (unsigned)(cm % NBUF) * B_BYTES;
#pragma unroll
            for (int ks = 0; ks < 4; ks++) {
                unsigned afr[2][4];
                ldsm_x4(afr[0], Ac + arowb[0] + cbx[ks]);
                ldsm_x4(afr[1], Ac + arowb[1] + cbx[ks]);
                unsigned bfr[2][4];
                ldsm_x4(bfr[0], Bc + browb[0] + cbx[ks]);
                ldsm_x4(bfr[1], Bc + browb[1] + cbx[ks]);
#pragma unroll
                for (int mf = 0; mf < 2; mf++)
#pragma unroll
                    for (int nf = 0; nf < 4; nf++)
                        mma_fp8h(acc[mf][nf], afr[mf],
                                 bfr[nf >> 1][nf & 1],
                                 bfr[nf >> 1][2 + (nf & 1)]);
            }
            // consumer->producer: before NEXT overwrite of this group's rows of
            // this slot (chunk cm+3, issued after the NEXT GBAR) all 4 warps of
            // the group have finished reading — guaranteed by that next GBAR.
            cm++;
        }

        // ---- epilogue (f32) ----
        bool isdiag = (J == I);
        bool ispos  = (J == I + 32);

        if (isdiag | ispos) {
#pragma unroll
            for (int mf = 0; mf < 2; mf++)
#pragma unroll
                for (int h = 0; h < 2; h++) {
                    int rloc = warpM * 32 + mf * 16 + h * 8 + qrow;
                    int cc = rloc - warpN * 32;
                    if (cc >= 0 && cc < 32 && (((cc >> 1) & 3) == (lane & 3))) {
                        __half2 hp = *(__half2*)&acc[mf][cc >> 3][h];
                        float v = (cc & 1) ? __high2float(hp) : __low2float(hp);
                        if (isdiag) rsum[mf][h] -= ex2s(v);
                        if (ispos) {
                            g_pos[rowbase + rloc] = v * PSC;
                            g_pos[rowbase + rloc + BHALF] = v * PSC;
                        }
                    }
                }
        }

        float colp[8];
#pragma unroll
        for (int q = 0; q < 8; q++) colp[q] = 0.f;
#pragma unroll
        for (int mf = 0; mf < 2; mf++) {
            float slo = 0.f, shi = 0.f;
#pragma unroll
            for (int nf = 0; nf < 4; nf++) {
                float2 f01 = __half22float2(*(__half2*)&acc[mf][nf][0]);
                float2 f23 = __half22float2(*(__half2*)&acc[mf][nf][1]);
                float e0 = ex2s(f01.x);
                float e1 = ex2s(f01.y);
                float e2 = ex2s(f23.x);
                float e3 = ex2s(f23.y);
                slo += e0 + e1;
                shi += e2 + e3;
                colp[nf * 2]     += e0 + e2;
                colp[nf * 2 + 1] += e1 + e3;
            }
            rsum[mf][0] += slo;
            rsum[mf][1] += shi;
        }

        if (!isdiag) {
#pragma unroll
            for (int q = 0; q < 8; q++) {
                float v = colp[q];
                v += __shfl_xor_sync(0xFFFFFFFFu, v, 4);
                v += __shfl_xor_sync(0xFFFFFFFFu, v, 8);
                v += __shfl_xor_sync(0xFFFFFFFFu, v, 16);
                if (lane < 4) {
                    int ccol = (q >> 1) * 8 + 2 * lane + (q & 1);
                    atomicAdd(&g_rowsum[colbase + warpN * 32 + ccol], v);
                }
            }
        }
    }

    // final row flush
#pragma unroll
    for (int mf = 0; mf < 2; mf++)
#pragma unroll
        for (int h = 0; h < 2; h++) {
            float v = rsum[mf][h];
            v += __shfl_xor_sync(0xFFFFFFFFu, v, 1);
            v += __shfl_xor_sync(0xFFFFFFFFu, v, 2);
            if ((lane & 3) == 0 && curI >= 0)
                atomicAdd(&g_rowsum[(curI << 7) + warpM * 32 + mf * 16 + h * 8 + qrow], v);
        }

    // ---- completion ticket: last CTA computes the loss ----
    __threadfence();
    __syncthreads();
    __shared__ unsigned ticket;
    if (tid == 0) ticket = atomicAdd(&g_done, 1u);
    __syncthreads();
    if (ticket == NCTAS - 1) {
        float local_s = 0.f;
        for (int r = tid; r < NN; r += NTHR)
            local_s += (1.0f - g_pos[r]) * INV_TAU + __logf(g_rowsum[r]);
#pragma unroll
        for (int o = 16; o > 0; o >>= 1) local_s += __shfl_xor_sync(0xFFFFFFFFu, local_s, o);
        __shared__ float red[16];
        if (lane == 0) red[wid] = local_s;
        __syncthreads();
        if (tid < 16) {
            float v = red[tid];
#pragma unroll
            for (int o = 8; o > 0; o >>= 1) v += __shfl_xor_sync(0xFFFFu, v, o);
            if (tid == 0) out[0] = v * (1.0f / (float)NN);
        }
    }
}

// ---------------------------------------------------------------------------
extern "C" void kernel_launch(void* const* d_in, const int* in_sizes, int n_in,
                              void* d_out, int out_size) {
    (void)in_sizes; (void)n_in; (void)out_size;
    const float* anchor   = (const float*)d_in[0];
    const float* positive = (const float*)d_in[1];

    cudaFuncSetAttribute(ntx_main, cudaFuncAttributeMaxDynamicSharedMemorySize,
                         SMEM_BYTES);

    ntx_normalize<<<NN / 8, 256>>>(anchor, positive);
    ntx_main<<<NCTAS, NTHR, SMEM_BYTES>>>((float*)d_out);
}

// round 14
// speedup vs baseline: 1.0376x; 1.0214x over previous
#include <cuda_runtime.h>
#include <cuda_bf16.h>
#include <cuda_fp16.h>

// ---------------------------------------------------------------------------
// NT-Xent loss, N=8192, D=512. FP8 (e4m3, scale 16) mma.sync m16n8k32 with
// f16 accumulation (2x rate), upper-triangular tiles (S = Z Z^T symmetric).
// Epilogue: exp via fma.rn.f16x2 + ex2.approx.f16x2 straight on the f16x2
// accumulators (exponent biased +15 to stay f16-normal; bias removed in the
// final log; diagonal cancelled bitwise-exactly), sums in f32.
// 296 CTAs x 512 threads, 2 CTAs/SM. Final logsumexp fused via ticket.
// ---------------------------------------------------------------------------

#define NN      8192
#define DD      512
#define BHALF   4096
#define NCHUNK  4            // 512 fp8 bytes / 128-byte chunk
#define NTILES  2080
#define NCTAS   296
#define NTHR    512

#define PSC     0.00390625f               // 1/256
#define INV_TAU 14.285714285714286f
// f16 constants: E = rn16(log2e/0.07/256) = 0x2D27, C = rn16(15-20.60993) = 0xC59C
#define E2U     0x2D272D27u
#define NC2U    0xC59CC59Cu
// final log correction: ln2 * (20.6099291555662 - 5.609375) = ln2 * 15.00055416
#define LOGC    10.3975918f

#define A_BYTES  65536       // 128 rows x 512 B (4 chunks x 16 KB)
#define B_OFF    65536
#define B_BYTES  16384       // one B chunk: 128 rows x 128 B
#define SMEM_BYTES (A_BYTES + 2*B_BYTES + 1024)

__device__ __align__(128) unsigned char g_z[(size_t)NN * DD];   // e4m3, x16
__device__ float g_rowsum[NN];
__device__ float g_pos[NN];
__device__ unsigned g_done;

// ------------------------------- helpers -----------------------------------
__device__ __forceinline__ unsigned smem_u32(const void* p) {
    unsigned a;
    asm("{ .reg .u64 t; cvta.to.shared.u64 t, %1; cvt.u32.u64 %0, t; }"
        : "=r"(a) : "l"(p));
    return a;
}
__device__ __forceinline__ unsigned swz(unsigned off) {
    return off ^ ((off >> 3) & 0x70);
}
__device__ __forceinline__ void cp16(unsigned dst, const void* src) {
    asm volatile("cp.async.cg.shared.global [%0], [%1], 16;"
                 :: "r"(dst), "l"(src) : "memory");
}
#define CP_COMMIT() asm volatile("cp.async.commit_group;" ::: "memory")
#define CP_WAIT(n)  asm volatile("cp.async.wait_group %0;" :: "n"(n) : "memory")

__device__ __forceinline__ void ldsm_x4(unsigned* r, unsigned addr) {
    asm volatile("ldmatrix.sync.aligned.m8n8.x4.shared.b16 {%0,%1,%2,%3}, [%4];"
                 : "=r"(r[0]), "=r"(r[1]), "=r"(r[2]), "=r"(r[3]) : "r"(addr));
}
// fp8 mma, f16 accumulator (c0: rows lane>>2, cols 2*(lane&3)+{0,1}; c1: row+8)
__device__ __forceinline__ void mma_fp8h(unsigned* c, const unsigned* a,
                                         unsigned b0, unsigned b1) {
    asm volatile(
        "mma.sync.aligned.m16n8k32.row.col.f16.e4m3.e4m3.f16 "
        "{%0,%1}, {%2,%3,%4,%5}, {%6,%7}, {%0,%1};"
        : "+r"(c[0]), "+r"(c[1])
        : "r"(a[0]), "r"(a[1]), "r"(a[2]), "r"(a[3]), "r"(b0), "r"(b1));
}
__device__ __forceinline__ unsigned hfma2u(unsigned a, unsigned b, unsigned c) {
    unsigned d; asm("fma.rn.f16x2 %0,%1,%2,%3;" : "=r"(d) : "r"(a), "r"(b), "r"(c));
    return d;
}
__device__ __forceinline__ unsigned h2ex2(unsigned a) {
    unsigned d; asm("ex2.approx.f16x2 %0,%1;" : "=r"(d) : "r"(a));
    return d;
}
__device__ __forceinline__ float2 h2f2(unsigned a) {
    __half2 h = *(__half2*)&a;
    return __half22float2(h);
}
__device__ __forceinline__ unsigned short cvt2_e4m3(float lo, float hi) {
    unsigned short r;
    asm("cvt.rn.satfinite.e4m3x2.f32 %0, %1, %2;" : "=h"(r) : "f"(hi), "f"(lo));
    return r;
}

// decode flattened tile index -> (I, J)
__device__ __forceinline__ void tile_decode(int t, int& I, int& J) {
    int p = t / 65;
    int l = t - p * 65;
    int n1 = 64 - p;
    if (l < n1) { I = p;      J = p + l; }
    else        { I = 63 - p; J = I + (l - n1); }
}

// ------------------------- kernel 1: normalize -> fp8 ----------------------
__global__ __launch_bounds__(256) void ntx_normalize(const float* __restrict__ anchor,
                                                     const float* __restrict__ positive) {
    int gt = blockIdx.x * 256 + threadIdx.x;
    if (gt < NN) g_rowsum[gt] = 0.f;          // graph-replay safe re-init
    if (gt == 0) g_done = 0u;

    int row  = blockIdx.x * 8 + (threadIdx.x >> 5);
    int lane = threadIdx.x & 31;
    const float* src = (row < BHALF) ? (anchor + (size_t)row * DD)
                                     : (positive + (size_t)(row - BHALF) * DD);
    const float4* s4 = (const float4*)src;
    float4 v[4];
    float ss = 0.f;
#pragma unroll
    for (int q = 0; q < 4; q++) {
        v[q] = s4[lane + 32 * q];
        ss += v[q].x * v[q].x + v[q].y * v[q].y + v[q].z * v[q].z + v[q].w * v[q].w;
    }
#pragma unroll
    for (int o = 16; o > 0; o >>= 1) ss += __shfl_xor_sync(0xFFFFFFFFu, ss, o);
    float s16 = 16.0f / fmaxf(sqrtf(ss), 1e-8f);

    unsigned* zp = (unsigned*)(g_z + (size_t)row * DD);
#pragma unroll
    for (int q = 0; q < 4; q++) {
        unsigned lo = cvt2_e4m3(v[q].x * s16, v[q].y * s16);
        unsigned hi = cvt2_e4m3(v[q].z * s16, v[q].w * s16);
        zp[lane + 32 * q] = lo | (hi << 16);
    }
}

// ------------------------- kernel 2: upper-tri GEMM + exp-reduce -----------
__device__ __forceinline__ void issueB(unsigned bbase, int colbase, int k, int tid) {
#pragma unroll
    for (int it = 0; it < 2; it++) {
        int idx = tid + it * NTHR;
        int r = idx >> 3, c8 = idx & 7;
        const void* src = g_z + ((size_t)(colbase + r) << 9) + k * 128 + c8 * 16;
        cp16(bbase + swz((unsigned)(r * 128 + c8 * 16)), src);
    }
}

// ring depth 2: slot = m & 1
__device__ __forceinline__ void issue_chunk(unsigned Bb, int t0, int t1, int m, int tid) {
    int tt = t0 + (m >> 2);
    if (tt < t1) {
        int I2, J2;
        tile_decode(tt, I2, J2);
        issueB(Bb + (unsigned)(m & 1) * B_BYTES, J2 << 7, m & 3, tid);
    }
    CP_COMMIT();
}

__global__ __launch_bounds__(NTHR, 2) void ntx_main(float* __restrict__ out) {
    extern __shared__ char smem_raw[];
    unsigned raw  = smem_u32(smem_raw);
    unsigned base = (raw + 1023u) & ~1023u;
    char* sp      = smem_raw + (base - raw);
    unsigned A  = base;
    unsigned Bb = base + B_OFF;

    int tid  = threadIdx.x;
    int wid  = tid >> 5, lane = tid & 31;
    int warpM = wid & 3, warpN = wid >> 2;     // 4 x 4 warp grid, tile 32x32
    int qrow = lane >> 2;

    int c  = blockIdx.x;
    int t0 = (c * NTILES) / NCTAS;
    int t1 = ((c + 1) * NTILES) / NCTAS;

    // compact ldmatrix addressing
    int sel = lane >> 3, lr = lane & 7;
    unsigned cbx[4];
#pragma unroll
    for (int ks = 0; ks < 4; ks++)
        cbx[ks] = ((unsigned)(ks * 32 + ((sel >> 1) << 4))) ^ ((unsigned)lr << 4);
    unsigned arowb[2];
#pragma unroll
    for (int mf = 0; mf < 2; mf++)
        arowb[mf] = (unsigned)((warpM * 32 + mf * 16 + ((sel & 1) << 3) + lr) * 128);
    unsigned browb[2];
#pragma unroll
    for (int p = 0; p < 2; p++)
        browb[p] = (unsigned)((warpN * 32 + p * 16 + ((sel & 1) << 3) + lr) * 128);

    issue_chunk(Bb, t0, t1, 0, tid);

    unsigned acc[2][4][2];                     // f16x2 accumulators (32x32 tile)
    float rsum[2][2] = {{0.f, 0.f}, {0.f, 0.f}};
    int curI = -1;
    int cm = 0;

    for (int t = t0; t < t1; t++) {
        int I, J;
        tile_decode(t, I, J);
        int rowbase = I << 7, colbase = J << 7;

        if (I != curI) {
            if (curI >= 0) {
#pragma unroll
                for (int mf = 0; mf < 2; mf++)
#pragma unroll
                    for (int h = 0; h < 2; h++) {
                        float v = rsum[mf][h];
                        v += __shfl_xor_sync(0xFFFFFFFFu, v, 1);
                        v += __shfl_xor_sync(0xFFFFFFFFu, v, 2);
                        if ((lane & 3) == 0)
                            atomicAdd(&g_rowsum[(curI << 7) + warpM * 32 + mf * 16 + h * 8 + qrow], v);
                        rsum[mf][h] = 0.f;
                    }
            }
            __syncthreads();                   // all readers of old A done
#pragma unroll
            for (int it = 0; it < 8; it++) {
                int x = tid + it * NTHR;
                int r = x >> 5, u = x & 31, ck = u >> 3, c8 = u & 7;
                const uint4* src = (const uint4*)(g_z + ((size_t)(rowbase + r) << 9)
                                                  + ck * 128 + c8 * 16);
                *(uint4*)(sp + ck * 16384 + swz((unsigned)(r * 128 + c8 * 16))) = *src;
            }
            __syncthreads();
            curI = I;
        }

#pragma unroll
        for (int mf = 0; mf < 2; mf++)
#pragma unroll
            for (int nf = 0; nf < 4; nf++) {
                acc[mf][nf][0] = 0u;
                acc[mf][nf][1] = 0u;
            }

#pragma unroll
        for (int k = 0; k < NCHUNK; k++) {
            CP_WAIT(0);
            __syncthreads();
            issue_chunk(Bb, t0, t1, cm + 1, tid);

            unsigned Ac = A + k * 16384;
            unsigned Bc = Bb + (unsigned)(cm & 1) * B_BYTES;
#pragma unroll
            for (int ks = 0; ks < 4; ks++) {
                unsigned afr[2][4];
                ldsm_x4(afr[0], Ac + arowb[0] + cbx[ks]);
                ldsm_x4(afr[1], Ac + arowb[1] + cbx[ks]);
                unsigned bfr[2][4];
                ldsm_x4(bfr[0], Bc + browb[0] + cbx[ks]);
                ldsm_x4(bfr[1], Bc + browb[1] + cbx[ks]);
#pragma unroll
                for (int mf = 0; mf < 2; mf++)
#pragma unroll
                    for (int nf = 0; nf < 4; nf++)
                        mma_fp8h(acc[mf][nf], afr[mf],
                                 bfr[nf >> 1][nf & 1],
                                 bfr[nf >> 1][2 + (nf & 1)]);
            }
            cm++;
        }

        // ---- epilogue: f16x2 fma+ex2 (bias +15), f32 sums ----
        bool isdiag = (J == I);
        bool ispos  = (J == I + 32);

        if (isdiag | ispos) {
#pragma unroll
            for (int mf = 0; mf < 2; mf++)
#pragma unroll
                for (int h = 0; h < 2; h++) {
                    int rloc = warpM * 32 + mf * 16 + h * 8 + qrow;
                    int cc = rloc - warpN * 32;
                    if (cc >= 0 && cc < 32 && (((cc >> 1) & 3) == (lane & 3))) {
                        unsigned hp = acc[mf][cc >> 3][h];
                        if (isdiag) {
                            // identical f16 recompute -> bitwise-exact cancel
                            float2 fe = h2f2(h2ex2(hfma2u(hp, E2U, NC2U)));
                            rsum[mf][h] -= (cc & 1) ? fe.y : fe.x;
                        }
                        if (ispos) {
                            __half2 hv = *(__half2*)&hp;
                            float v = (cc & 1) ? __high2float(hv) : __low2float(hv);
                            g_pos[rowbase + rloc] = v * PSC;
                            g_pos[rowbase + rloc + BHALF] = v * PSC;
                        }
                    }
                }
        }

        float colp[8];
#pragma unroll
        for (int q = 0; q < 8; q++) colp[q] = 0.f;
#pragma unroll
        for (int mf = 0; mf < 2; mf++) {
            float slo = 0.f, shi = 0.f;
#pragma unroll
            for (int nf = 0; nf < 4; nf++) {
                unsigned eh0 = h2ex2(hfma2u(acc[mf][nf][0], E2U, NC2U));
                unsigned eh1 = h2ex2(hfma2u(acc[mf][nf][1], E2U, NC2U));
                float2 f01 = h2f2(eh0);        // (col even, col odd) row qrow
                float2 f23 = h2f2(eh1);        // (col even, col odd) row qrow+8
                slo += f01.x + f01.y;
                shi += f23.x + f23.y;
                colp[nf * 2]     += f01.x + f23.x;
                colp[nf * 2 + 1] += f01.y + f23.y;
            }
            rsum[mf][0] += slo;
            rsum[mf][1] += shi;
        }

        if (!isdiag) {
#pragma unroll
            for (int q = 0; q < 8; q++) {
                float v = colp[q];
                v += __shfl_xor_sync(0xFFFFFFFFu, v, 4);
                v += __shfl_xor_sync(0xFFFFFFFFu, v, 8);
                v += __shfl_xor_sync(0xFFFFFFFFu, v, 16);
                if (lane < 4) {
                    int ccol = (q >> 1) * 8 + 2 * lane + (q & 1);
                    atomicAdd(&g_rowsum[colbase + warpN * 32 + ccol], v);
                }
            }
        }
    }

    // final row flush
#pragma unroll
    for (int mf = 0; mf < 2; mf++)
#pragma unroll
        for (int h = 0; h < 2; h++) {
            float v = rsum[mf][h];
            v += __shfl_xor_sync(0xFFFFFFFFu, v, 1);
            v += __shfl_xor_sync(0xFFFFFFFFu, v, 2);
            if ((lane & 3) == 0 && curI >= 0)
                atomicAdd(&g_rowsum[(curI << 7) + warpM * 32 + mf * 16 + h * 8 + qrow], v);
        }

    // ---- completion ticket: last CTA computes the loss ----
    __threadfence();
    __syncthreads();
    __shared__ unsigned ticket;
    if (tid == 0) ticket = atomicAdd(&g_done, 1u);
    __syncthreads();
    if (ticket == NCTAS - 1) {
        float local_s = 0.f;
        for (int r = tid; r < NN; r += NTHR)
            local_s += (1.0f - g_pos[r]) * INV_TAU + __logf(g_rowsum[r]) - LOGC;
#pragma unroll
        for (int o = 16; o > 0; o >>= 1) local_s += __shfl_xor_sync(0xFFFFFFFFu, local_s, o);
        __shared__ float red[16];
        if (lane == 0) red[wid] = local_s;
        __syncthreads();
        if (tid < 16) {
            float v = red[tid];
#pragma unroll
            for (int o = 8; o > 0; o >>= 1) v += __shfl_xor_sync(0xFFFFu, v, o);
            if (tid == 0) out[0] = v * (1.0f / (float)NN);
        }
    }
}

// ---------------------------------------------------------------------------
extern "C" void kernel_launch(void* const* d_in, const int* in_sizes, int n_in,
                              void* d_out, int out_size) {
    (void)in_sizes; (void)n_in; (void)out_size;
    const float* anchor   = (const float*)d_in[0];
    const float* positive = (const float*)d_in[1];

    cudaFuncSetAttribute(ntx_main, cudaFuncAttributeMaxDynamicSharedMemorySize,
                         SMEM_BYTES);

    ntx_normalize<<<NN / 8, 256>>>(anchor, positive);
    ntx_main<<<NCTAS, NTHR, SMEM_BYTES>>>((float*)d_out);
}